// round 12
// baseline (speedup 1.0000x reference)
#include <cuda_runtime.h>
#include <cstdint>

#define DEV __device__ __forceinline__

// ------------------------------- helpers -----------------------------------
DEV uint32_t smem_u32(const void* p) { return (uint32_t)__cvta_generic_to_shared(p); }

DEV float f2tf(float f) {   // round-to-nearest tf32 (HW mma truncates -> must pre-round)
    uint32_t u;
    asm("cvt.rna.tf32.f32 %0, %1;" : "=r"(u) : "f"(f));
    return __uint_as_float(u);
}

DEV void cp16(uint32_t dst, const void* src) {
    asm volatile("cp.async.cg.shared.global [%0], [%1], 16;" :: "r"(dst), "l"(src));
}
#define CP_COMMIT() asm volatile("cp.async.commit_group;")
#define CP_WAIT(N)  asm volatile("cp.async.wait_group %0;" :: "n"(N))

DEV void mma8(float* d, const uint32_t* a, const uint32_t* b) {
    asm volatile(
        "mma.sync.aligned.m16n8k8.row.col.f32.tf32.tf32.f32 "
        "{%0,%1,%2,%3}, {%4,%5,%6,%7}, {%8,%9}, {%0,%1,%2,%3};\n"
        : "+f"(d[0]), "+f"(d[1]), "+f"(d[2]), "+f"(d[3])
        : "r"(a[0]), "r"(a[1]), "r"(a[2]), "r"(a[3]), "r"(b[0]), "r"(b[1]));
}

// --------------------------- scratch (no cudaMalloc) ------------------------
__device__ float g_Aq [8192ull  * 1024];   // shifted + tf32-rounded query rows
__device__ float g_Akv[32768ull * 1024];   // tf32-rounded kv rows
__device__ float g_Wqc[1024 * 1024];
__device__ float g_Wkc[1024 * 1024];
__device__ float g_Wvc[1024 * 1024];
__device__ float g_Qp [8192ull  * 1024];   // projections (tf32-exact fp32)
__device__ float g_Kp [32768ull * 1024];
__device__ float g_Vp [32768ull * 1024];

// ----------------------------- convert kernels ------------------------------
__global__ void cvt_kernel(const float* __restrict__ src, float* __restrict__ dst, int n4) {
    int i = blockIdx.x * 256 + threadIdx.x;
    if (i >= n4) return;
    float4 v = ((const float4*)src)[i];
    v.x = f2tf(v.x); v.y = f2tf(v.y); v.z = f2tf(v.z); v.w = f2tf(v.w);
    ((float4*)dst)[i] = v;
}

// Aq row (b*2048 + j) = query[b, j+63] for j<1985 else 0, tf32-rounded
__global__ void cvtq_kernel(const float* __restrict__ query, float* __restrict__ dst) {
    int i = blockIdx.x * 256 + threadIdx.x;   // float4 index over [8192,256]
    int col4 = i & 255;
    int row  = i >> 8;
    int b    = row >> 11;
    int j    = row & 2047;
    float4 v = make_float4(0.f, 0.f, 0.f, 0.f);
    if (j < 1985)
        v = ((const float4*)query)[(size_t)((b << 11) + j + 63) * 256 + col4];
    v.x = f2tf(v.x); v.y = f2tf(v.y); v.z = f2tf(v.z); v.w = f2tf(v.w);
    ((float4*)dst)[i] = v;
}

// zero out[b, 0:63, :]
__global__ void zero_head(float* __restrict__ out) {
    int i = blockIdx.x * 256 + threadIdx.x;   // float4 index
    if (i >= 4 * 63 * 256) return;
    int b = i / (63 * 256);
    int r = i - b * (63 * 256);
    ((float4*)(out + (size_t)b * 2048 * 1024))[r] = make_float4(0.f, 0.f, 0.f, 0.f);
}

// ------------- tf32 GEMM: C[M,1024] = A[M,1024] @ W[1024,1024]^T + bias -----
// BM=BN=128, BK=16, 3-stage cp.async pipeline, 8 warps of 32(M)x64(N).
constexpr int GK_LDA   = 20;                 // 16 + 4 pad -> conflict-free frags
constexpr int GK_STAGE = 128 * GK_LDA;       // floats per operand per stage
constexpr int GEMM_SMEM = 3 * 2 * GK_STAGE * 4;   // 61440 B

__global__ void __launch_bounds__(256, 1)
gemm_tf32(const float* __restrict__ A, const float* __restrict__ B,
          const float* __restrict__ bias, float* __restrict__ C) {
    extern __shared__ float sm[];
    float* sA = sm;
    float* sB = sm + 3 * GK_STAGE;

    const int tid  = threadIdx.x;
    const int lane = tid & 31;
    const int wid  = tid >> 5;
    const int wm   = wid & 3;          // 4 warps along M
    const int wn   = wid >> 2;         // 2 warps along N
    const int lr   = lane >> 2;
    const int lc   = lane & 3;

    const float* gA = A + (size_t)blockIdx.y * 128 * 1024;
    const float* gB = B + (size_t)blockIdx.x * 128 * 1024;

    const int ldr = tid >> 2;                       // 0..63 (row in half-tile)
    const int ldc = (tid & 3) * 4;                  // 0,4,8,12 (k offset)
    const uint32_t sAw = smem_u32(sA) + (uint32_t)(ldr * GK_LDA + ldc) * 4u;
    const uint32_t sBw = smem_u32(sB) + (uint32_t)(ldr * GK_LDA + ldc) * 4u;
    const float* gAt = gA + (size_t)ldr * 1024 + ldc;
    const float* gBt = gB + (size_t)ldr * 1024 + ldc;

    float acc[2][8][4];
#pragma unroll
    for (int a = 0; a < 2; a++)
#pragma unroll
        for (int n = 0; n < 8; n++)
#pragma unroll
            for (int c = 0; c < 4; c++) acc[a][n][c] = 0.f;

#pragma unroll
    for (int s = 0; s < 2; s++) {                   // prefetch stages 0,1
        uint32_t da = sAw + s * (GK_STAGE * 4);
        uint32_t db = sBw + s * (GK_STAGE * 4);
        int kb = s * 16;
        cp16(da,                   gAt + kb);
        cp16(da + 64 * GK_LDA * 4, gAt + 64 * 1024 + kb);
        cp16(db,                   gBt + kb);
        cp16(db + 64 * GK_LDA * 4, gBt + 64 * 1024 + kb);
        CP_COMMIT();
    }

#pragma unroll 1
    for (int kt = 0; kt < 64; kt++) {
        CP_WAIT(1);
        __syncthreads();
        {
            int kn = kt + 2;
            if (kn < 64) {
                int s = kn % 3;
                uint32_t da = sAw + s * (GK_STAGE * 4);
                uint32_t db = sBw + s * (GK_STAGE * 4);
                int kb = kn * 16;
                cp16(da,                   gAt + kb);
                cp16(da + 64 * GK_LDA * 4, gAt + 64 * 1024 + kb);
                cp16(db,                   gBt + kb);
                cp16(db + 64 * GK_LDA * 4, gBt + 64 * 1024 + kb);
            }
            CP_COMMIT();
        }
        const int stage = kt % 3;
        const float* wA = sA + stage * GK_STAGE + (wm * 32) * GK_LDA;
        const float* wB = sB + stage * GK_STAGE + (wn * 64) * GK_LDA;
#pragma unroll
        for (int kk = 0; kk < 2; kk++) {
            const int k0 = kk * 8 + lc;
            uint32_t af[2][4];
            uint32_t bf[8][2];
#pragma unroll
            for (int mi = 0; mi < 2; mi++) {
                const float* p = wA + (mi * 16 + lr) * GK_LDA + k0;
                af[mi][0] = __float_as_uint(p[0]);
                af[mi][1] = __float_as_uint(p[8 * GK_LDA]);
                af[mi][2] = __float_as_uint(p[4]);
                af[mi][3] = __float_as_uint(p[8 * GK_LDA + 4]);
            }
#pragma unroll
            for (int ni = 0; ni < 8; ni++) {
                const float* p = wB + (ni * 8 + lr) * GK_LDA + k0;
                bf[ni][0] = __float_as_uint(p[0]);
                bf[ni][1] = __float_as_uint(p[4]);
            }
#pragma unroll
            for (int mi = 0; mi < 2; mi++)
#pragma unroll
                for (int ni = 0; ni < 8; ni++)
                    mma8(acc[mi][ni], af[mi], bf[ni]);
        }
    }

    // epilogue: +bias, tf32-round so the attention MMAs consume exact tf32
    const int mbase = blockIdx.y * 128 + wm * 32;
    const int nbase = blockIdx.x * 128 + wn * 64;
#pragma unroll
    for (int ni = 0; ni < 8; ni++) {
        int col = nbase + ni * 8 + lc * 2;
        float bx = bias[col];
        float by = bias[col + 1];
#pragma unroll
        for (int mi = 0; mi < 2; mi++) {
            int r0 = mbase + mi * 16 + lr;
            float2 v0, v1;
            v0.x = f2tf(acc[mi][ni][0] + bx);
            v0.y = f2tf(acc[mi][ni][1] + by);
            v1.x = f2tf(acc[mi][ni][2] + bx);
            v1.y = f2tf(acc[mi][ni][3] + by);
            *(float2*)(C + (size_t)r0 * 1024 + col)       = v0;
            *(float2*)(C + (size_t)(r0 + 8) * 1024 + col) = v1;
        }
    }
}

// -------------------------------- attention ---------------------------------
// One CTA per (head, chunk, batch). 256 threads (8 warps).
// smem: q[64x68] | k[256x68] (reused as P[64x260]) | vT[64x260]
constexpr int LQ = 68;
constexpr int LP = 260;
constexpr int ATTN_SMEM = (64 * LQ + 256 * LQ + 64 * LP) * 4;   // 153600 B

__global__ void __launch_bounds__(256, 1)
attn_kernel(const float* __restrict__ Qp, const float* __restrict__ Kp,
            const float* __restrict__ Vp, float* __restrict__ out) {
    extern __shared__ float sm[];
    float* q_s  = sm;                  // 64*68
    float* kp_s = sm + 64 * LQ;        // 256*68 (later reused as P 64*260)
    float* vt_s = kp_s + 256 * LQ;     // 64*260

    const int h = blockIdx.x, c = blockIdx.y, b = blockIdx.z;
    const int tid = threadIdx.x, lane = tid & 31, wid = tid >> 5;
    const int lr = lane >> 2, lc = lane & 3;

    const float* Qg = Qp + (size_t)(b * 2048 + c * 64) * 1024 + h * 64;
    const float* Kg = Kp + (size_t)((b * 32 + c) * 256) * 1024 + h * 64;
    const float* Vg = Vp + (size_t)((b * 32 + c) * 256) * 1024 + h * 64;

    // q: 64x64 -> 1024 float4 (cp.async)
#pragma unroll
    for (int t = 0; t < 4; t++) {
        int idx = tid + t * 256;
        int r = idx >> 4, c4 = (idx & 15) << 2;
        cp16(smem_u32(q_s + r * LQ + c4), Qg + (size_t)r * 1024 + c4);
    }
    // k: 256x64 -> 4096 float4 (cp.async)
#pragma unroll
    for (int t = 0; t < 16; t++) {
        int idx = tid + t * 256;
        int r = idx >> 4, c4 = (idx & 15) << 2;
        cp16(smem_u32(kp_s + r * LQ + c4), Kg + (size_t)r * 1024 + c4);
    }
    CP_COMMIT();
    // v transposed: coalesced LDG.128, scalar STS (overlaps the cp.async)
#pragma unroll
    for (int t = 0; t < 16; t++) {
        int idx = tid + t * 256;
        int r = idx >> 4, c4 = (idx & 15) << 2;
        float4 v = *(const float4*)(Vg + (size_t)r * 1024 + c4);
        vt_s[(c4 + 0) * LP + r] = v.x;
        vt_s[(c4 + 1) * LP + r] = v.y;
        vt_s[(c4 + 2) * LP + r] = v.z;
        vt_s[(c4 + 3) * LP + r] = v.w;
    }
    CP_WAIT(0);
    __syncthreads();

    // ---- S = (q @ k^T) * 0.125 ---- warps: 2(M) x 4(N), each 32x64
    {
        const int wm = wid & 1, wn = wid >> 1;
        float acc[2][8][4];
#pragma unroll
        for (int a = 0; a < 2; a++)
#pragma unroll
            for (int n = 0; n < 8; n++)
#pragma unroll
                for (int k = 0; k < 4; k++) acc[a][n][k] = 0.f;

        const float* wA = q_s  + (wm * 32) * LQ;
        const float* wB = kp_s + (wn * 64) * LQ;
#pragma unroll
        for (int k8 = 0; k8 < 8; k8++) {
            int k0 = k8 * 8 + lc;
            uint32_t af[2][4], bf[8][2];
#pragma unroll
            for (int mi = 0; mi < 2; mi++) {
                const float* p = wA + (mi * 16 + lr) * LQ + k0;
                af[mi][0] = __float_as_uint(p[0]);
                af[mi][1] = __float_as_uint(p[8 * LQ]);
                af[mi][2] = __float_as_uint(p[4]);
                af[mi][3] = __float_as_uint(p[8 * LQ + 4]);
            }
#pragma unroll
            for (int ni = 0; ni < 8; ni++) {
                const float* p = wB + (ni * 8 + lr) * LQ + k0;
                bf[ni][0] = __float_as_uint(p[0]);
                bf[ni][1] = __float_as_uint(p[4]);
            }
#pragma unroll
            for (int mi = 0; mi < 2; mi++)
#pragma unroll
                for (int ni = 0; ni < 8; ni++)
                    mma8(acc[mi][ni], af[mi], bf[ni]);
        }
        __syncthreads();   // all k reads done before overwriting region as P
        float* Ps = kp_s;
#pragma unroll
        for (int mi = 0; mi < 2; mi++)
#pragma unroll
            for (int ni = 0; ni < 8; ni++) {
                int row = wm * 32 + mi * 16 + lr;
                int col = wn * 64 + ni * 8 + lc * 2;
                Ps[row * LP + col]           = acc[mi][ni][0] * 0.125f;
                Ps[row * LP + col + 1]       = acc[mi][ni][1] * 0.125f;
                Ps[(row + 8) * LP + col]     = acc[mi][ni][2] * 0.125f;
                Ps[(row + 8) * LP + col + 1] = acc[mi][ni][3] * 0.125f;
            }
    }
    __syncthreads();

    // ---- softmax over 256 cols; 4 lanes per row ----
    {
        float* p = kp_s + (tid >> 2) * LP + (tid & 3) * 64;
        float mx = -1e30f;
#pragma unroll 8
        for (int j = 0; j < 64; j++) mx = fmaxf(mx, p[j]);
        mx = fmaxf(mx, __shfl_xor_sync(0xffffffffu, mx, 1));
        mx = fmaxf(mx, __shfl_xor_sync(0xffffffffu, mx, 2));
        float sum = 0.f;
#pragma unroll 8
        for (int j = 0; j < 64; j++) { float e = __expf(p[j] - mx); p[j] = e; sum += e; }
        sum += __shfl_xor_sync(0xffffffffu, sum, 1);
        sum += __shfl_xor_sync(0xffffffffu, sum, 2);
        float inv = 1.f / sum;
#pragma unroll 8
        for (int j = 0; j < 64; j++) p[j] = f2tf(p[j] * inv);
    }
    __syncthreads();

    // ---- O = P @ V ---- warps: 4(M) x 2(N), each 16x32, k=256
    {
        const int wm = wid & 3, wn = wid >> 2;
        float acc[4][4];
#pragma unroll
        for (int n = 0; n < 4; n++)
#pragma unroll
            for (int k = 0; k < 4; k++) acc[n][k] = 0.f;

        const float* wA = kp_s + (wm * 16) * LP;
        const float* wB = vt_s + (wn * 32) * LP;
#pragma unroll 4
        for (int k8 = 0; k8 < 32; k8++) {
            int k0 = k8 * 8 + lc;
            uint32_t af[4];
            const float* pa = wA + lr * LP + k0;
            af[0] = __float_as_uint(pa[0]);
            af[1] = __float_as_uint(pa[8 * LP]);
            af[2] = __float_as_uint(pa[4]);
            af[3] = __float_as_uint(pa[8 * LP + 4]);
#pragma unroll
            for (int ni = 0; ni < 4; ni++) {
                const float* pb = wB + (ni * 8 + lr) * LP + k0;
                uint32_t bf[2] = { __float_as_uint(pb[0]), __float_as_uint(pb[4]) };
                mma8(acc[ni], af, bf);
            }
        }
        // shifted epilogue: out[b, r+63, h*64 + d], valid while r <= 1984
        const int hbase = h * 64 + wn * 32;
#pragma unroll
        for (int ni = 0; ni < 4; ni++) {
            int colg = hbase + ni * 8 + lc * 2;
            int r0 = c * 64 + wm * 16 + lr;
            if (r0 <= 1984) {
                float2 v; v.x = acc[ni][0]; v.y = acc[ni][1];
                *(float2*)(out + (size_t)(b * 2048 + r0 + 63) * 1024 + colg) = v;
            }
            int r1 = r0 + 8;
            if (r1 <= 1984) {
                float2 v; v.x = acc[ni][2]; v.y = acc[ni][3];
                *(float2*)(out + (size_t)(b * 2048 + r1 + 63) * 1024 + colg) = v;
            }
        }
    }
}

// -------------------------------- launcher ----------------------------------
extern "C" void kernel_launch(void* const* d_in, const int* in_sizes, int n_in,
                              void* d_out, int out_size) {
    const float* query = (const float*)d_in[0];
    const float* kv    = (const float*)d_in[1];
    const float* Wq    = (const float*)d_in[2];
    const float* bq    = (const float*)d_in[3];
    const float* Wk    = (const float*)d_in[4];
    const float* bk    = (const float*)d_in[5];
    const float* Wv    = (const float*)d_in[6];
    const float* bv    = (const float*)d_in[7];
    float* out = (float*)d_out;

    float *Aq, *Akv, *Wqc, *Wkc, *Wvc, *Qp, *Kp, *Vp;
    cudaGetSymbolAddress((void**)&Aq,  g_Aq);
    cudaGetSymbolAddress((void**)&Akv, g_Akv);
    cudaGetSymbolAddress((void**)&Wqc, g_Wqc);
    cudaGetSymbolAddress((void**)&Wkc, g_Wkc);
    cudaGetSymbolAddress((void**)&Wvc, g_Wvc);
    cudaGetSymbolAddress((void**)&Qp,  g_Qp);
    cudaGetSymbolAddress((void**)&Kp,  g_Kp);
    cudaGetSymbolAddress((void**)&Vp,  g_Vp);

    cudaFuncSetAttribute(gemm_tf32,  cudaFuncAttributeMaxDynamicSharedMemorySize, GEMM_SMEM);
    cudaFuncSetAttribute(attn_kernel, cudaFuncAttributeMaxDynamicSharedMemorySize, ATTN_SMEM);

    // 1) tf32-round + shift/pad activations and weights
    cvtq_kernel<<<8192, 256>>>(query, Aq);
    cvt_kernel <<<32768, 256>>>(kv, Akv, 32768 * 256);
    cvt_kernel <<<1024, 256>>>(Wq, Wqc, 256 * 1024);
    cvt_kernel <<<1024, 256>>>(Wk, Wkc, 256 * 1024);
    cvt_kernel <<<1024, 256>>>(Wv, Wvc, 256 * 1024);

    // 2) projections
    gemm_tf32<<<dim3(8, 64),  256, GEMM_SMEM>>>(Aq,  Wqc, bq, Qp);
    gemm_tf32<<<dim3(8, 256), 256, GEMM_SMEM>>>(Akv, Wkc, bk, Kp);
    gemm_tf32<<<dim3(8, 256), 256, GEMM_SMEM>>>(Akv, Wvc, bv, Vp);

    // 3) output head rows [0,63) zeroed; attention writes the rest
    zero_head<<<(4 * 63 * 256 + 255) / 256, 256>>>(out);
    attn_kernel<<<dim3(16, 32, 4), 256, ATTN_SMEM>>>(Qp, Kp, Vp, out);
}

// round 13
// speedup vs baseline: 1.0000x; 1.0000x over previous
#include <cuda_runtime.h>
#include <cstdint>

#define DEV __device__ __forceinline__

// ------------------------------- helpers -----------------------------------
DEV uint32_t smem_u32(const void* p) { return (uint32_t)__cvta_generic_to_shared(p); }

DEV float f2tf(float f) {   // round-to-nearest tf32 (HW mma truncates -> must pre-round)
    uint32_t u;
    asm("cvt.rna.tf32.f32 %0, %1;" : "=r"(u) : "f"(f));
    return __uint_as_float(u);
}

DEV void cp16(uint32_t dst, const void* src) {
    asm volatile("cp.async.cg.shared.global [%0], [%1], 16;" :: "r"(dst), "l"(src));
}
#define CP_COMMIT() asm volatile("cp.async.commit_group;")
#define CP_WAIT(N)  asm volatile("cp.async.wait_group %0;" :: "n"(N))

DEV void mma8(float* d, const uint32_t* a, const uint32_t* b) {
    asm volatile(
        "mma.sync.aligned.m16n8k8.row.col.f32.tf32.tf32.f32 "
        "{%0,%1,%2,%3}, {%4,%5,%6,%7}, {%8,%9}, {%0,%1,%2,%3};\n"
        : "+f"(d[0]), "+f"(d[1]), "+f"(d[2]), "+f"(d[3])
        : "r"(a[0]), "r"(a[1]), "r"(a[2]), "r"(a[3]), "r"(b[0]), "r"(b[1]));
}

// --------------------------- scratch (no cudaMalloc) ------------------------
__device__ float g_Aq [8192ull  * 1024];   // shifted + tf32-rounded query rows
__device__ float g_Akv[32768ull * 1024];   // tf32-rounded kv rows
__device__ float g_Wqc[1024 * 1024];
__device__ float g_Wkc[1024 * 1024];
__device__ float g_Wvc[1024 * 1024];
__device__ float g_Qp [8192ull  * 1024];   // projections (tf32-exact fp32)
__device__ float g_Kp [32768ull * 1024];
__device__ float g_Vp [32768ull * 1024];

// ----------------------------- convert kernels ------------------------------
__global__ void cvt_kernel(const float* __restrict__ src, float* __restrict__ dst, int n4) {
    int i = blockIdx.x * 256 + threadIdx.x;
    if (i >= n4) return;
    float4 v = ((const float4*)src)[i];
    v.x = f2tf(v.x); v.y = f2tf(v.y); v.z = f2tf(v.z); v.w = f2tf(v.w);
    ((float4*)dst)[i] = v;
}

// Aq row (b*2048 + j) = query[b, j+63] for j<1985 else 0, tf32-rounded
__global__ void cvtq_kernel(const float* __restrict__ query, float* __restrict__ dst) {
    int i = blockIdx.x * 256 + threadIdx.x;   // float4 index over [8192,256]
    int col4 = i & 255;
    int row  = i >> 8;
    int b    = row >> 11;
    int j    = row & 2047;
    float4 v = make_float4(0.f, 0.f, 0.f, 0.f);
    if (j < 1985)
        v = ((const float4*)query)[(size_t)((b << 11) + j + 63) * 256 + col4];
    v.x = f2tf(v.x); v.y = f2tf(v.y); v.z = f2tf(v.z); v.w = f2tf(v.w);
    ((float4*)dst)[i] = v;
}

// zero out[b, 0:63, :]
__global__ void zero_head(float* __restrict__ out) {
    int i = blockIdx.x * 256 + threadIdx.x;   // float4 index
    if (i >= 4 * 63 * 256) return;
    int b = i / (63 * 256);
    int r = i - b * (63 * 256);
    ((float4*)(out + (size_t)b * 2048 * 1024))[r] = make_float4(0.f, 0.f, 0.f, 0.f);
}

// ------------- tf32 GEMM: C[M,1024] = A[M,1024] @ W[1024,1024]^T + bias -----
// BM=BN=128, BK=16, 3-stage cp.async pipeline, 8 warps of 32(M)x64(N).
constexpr int GK_LDA   = 20;                 // 16 + 4 pad -> conflict-free frags
constexpr int GK_STAGE = 128 * GK_LDA;       // floats per operand per stage
constexpr int GEMM_SMEM = 3 * 2 * GK_STAGE * 4;   // 61440 B

__global__ void __launch_bounds__(256, 1)
gemm_tf32(const float* __restrict__ A, const float* __restrict__ B,
          const float* __restrict__ bias, float* __restrict__ C) {
    extern __shared__ float sm[];
    float* sA = sm;
    float* sB = sm + 3 * GK_STAGE;

    const int tid  = threadIdx.x;
    const int lane = tid & 31;
    const int wid  = tid >> 5;
    const int wm   = wid & 3;          // 4 warps along M
    const int wn   = wid >> 2;         // 2 warps along N
    const int lr   = lane >> 2;
    const int lc   = lane & 3;

    const float* gA = A + (size_t)blockIdx.y * 128 * 1024;
    const float* gB = B + (size_t)blockIdx.x * 128 * 1024;

    const int ldr = tid >> 2;                       // 0..63 (row in half-tile)
    const int ldc = (tid & 3) * 4;                  // 0,4,8,12 (k offset)
    const uint32_t sAw = smem_u32(sA) + (uint32_t)(ldr * GK_LDA + ldc) * 4u;
    const uint32_t sBw = smem_u32(sB) + (uint32_t)(ldr * GK_LDA + ldc) * 4u;
    const float* gAt = gA + (size_t)ldr * 1024 + ldc;
    const float* gBt = gB + (size_t)ldr * 1024 + ldc;

    float acc[2][8][4];
#pragma unroll
    for (int a = 0; a < 2; a++)
#pragma unroll
        for (int n = 0; n < 8; n++)
#pragma unroll
            for (int c = 0; c < 4; c++) acc[a][n][c] = 0.f;

#pragma unroll
    for (int s = 0; s < 2; s++) {                   // prefetch stages 0,1
        uint32_t da = sAw + s * (GK_STAGE * 4);
        uint32_t db = sBw + s * (GK_STAGE * 4);
        int kb = s * 16;
        cp16(da,                   gAt + kb);
        cp16(da + 64 * GK_LDA * 4, gAt + 64 * 1024 + kb);
        cp16(db,                   gBt + kb);
        cp16(db + 64 * GK_LDA * 4, gBt + 64 * 1024 + kb);
        CP_COMMIT();
    }

#pragma unroll 1
    for (int kt = 0; kt < 64; kt++) {
        CP_WAIT(1);
        __syncthreads();
        {
            int kn = kt + 2;
            if (kn < 64) {
                int s = kn % 3;
                uint32_t da = sAw + s * (GK_STAGE * 4);
                uint32_t db = sBw + s * (GK_STAGE * 4);
                int kb = kn * 16;
                cp16(da,                   gAt + kb);
                cp16(da + 64 * GK_LDA * 4, gAt + 64 * 1024 + kb);
                cp16(db,                   gBt + kb);
                cp16(db + 64 * GK_LDA * 4, gBt + 64 * 1024 + kb);
            }
            CP_COMMIT();
        }
        const int stage = kt % 3;
        const float* wA = sA + stage * GK_STAGE + (wm * 32) * GK_LDA;
        const float* wB = sB + stage * GK_STAGE + (wn * 64) * GK_LDA;
#pragma unroll
        for (int kk = 0; kk < 2; kk++) {
            const int k0 = kk * 8 + lc;
            uint32_t af[2][4];
            uint32_t bf[8][2];
#pragma unroll
            for (int mi = 0; mi < 2; mi++) {
                const float* p = wA + (mi * 16 + lr) * GK_LDA + k0;
                af[mi][0] = __float_as_uint(p[0]);
                af[mi][1] = __float_as_uint(p[8 * GK_LDA]);
                af[mi][2] = __float_as_uint(p[4]);
                af[mi][3] = __float_as_uint(p[8 * GK_LDA + 4]);
            }
#pragma unroll
            for (int ni = 0; ni < 8; ni++) {
                const float* p = wB + (ni * 8 + lr) * GK_LDA + k0;
                bf[ni][0] = __float_as_uint(p[0]);
                bf[ni][1] = __float_as_uint(p[4]);
            }
#pragma unroll
            for (int mi = 0; mi < 2; mi++)
#pragma unroll
                for (int ni = 0; ni < 8; ni++)
                    mma8(acc[mi][ni], af[mi], bf[ni]);
        }
    }

    // epilogue: +bias, tf32-round so the attention MMAs consume exact tf32
    const int mbase = blockIdx.y * 128 + wm * 32;
    const int nbase = blockIdx.x * 128 + wn * 64;
#pragma unroll
    for (int ni = 0; ni < 8; ni++) {
        int col = nbase + ni * 8 + lc * 2;
        float bx = bias[col];
        float by = bias[col + 1];
#pragma unroll
        for (int mi = 0; mi < 2; mi++) {
            int r0 = mbase + mi * 16 + lr;
            float2 v0, v1;
            v0.x = f2tf(acc[mi][ni][0] + bx);
            v0.y = f2tf(acc[mi][ni][1] + by);
            v1.x = f2tf(acc[mi][ni][2] + bx);
            v1.y = f2tf(acc[mi][ni][3] + by);
            *(float2*)(C + (size_t)r0 * 1024 + col)       = v0;
            *(float2*)(C + (size_t)(r0 + 8) * 1024 + col) = v1;
        }
    }
}

// -------------------------------- attention ---------------------------------
// One CTA per (head, chunk, batch). 256 threads (8 warps).
// smem: q[64x68] | k[256x68] (reused as P[64x260]) | vT[64x260]
constexpr int LQ = 68;
constexpr int LP = 260;
constexpr int ATTN_SMEM = (64 * LQ + 256 * LQ + 64 * LP) * 4;   // 153600 B

__global__ void __launch_bounds__(256, 1)
attn_kernel(const float* __restrict__ Qp, const float* __restrict__ Kp,
            const float* __restrict__ Vp, float* __restrict__ out) {
    extern __shared__ float sm[];
    float* q_s  = sm;                  // 64*68
    float* kp_s = sm + 64 * LQ;        // 256*68 (later reused as P 64*260)
    float* vt_s = kp_s + 256 * LQ;     // 64*260

    const int h = blockIdx.x, c = blockIdx.y, b = blockIdx.z;
    const int tid = threadIdx.x, lane = tid & 31, wid = tid >> 5;
    const int lr = lane >> 2, lc = lane & 3;

    const float* Qg = Qp + (size_t)(b * 2048 + c * 64) * 1024 + h * 64;
    const float* Kg = Kp + (size_t)((b * 32 + c) * 256) * 1024 + h * 64;
    const float* Vg = Vp + (size_t)((b * 32 + c) * 256) * 1024 + h * 64;

    // q: 64x64 -> 1024 float4 (cp.async)
#pragma unroll
    for (int t = 0; t < 4; t++) {
        int idx = tid + t * 256;
        int r = idx >> 4, c4 = (idx & 15) << 2;
        cp16(smem_u32(q_s + r * LQ + c4), Qg + (size_t)r * 1024 + c4);
    }
    // k: 256x64 -> 4096 float4 (cp.async)
#pragma unroll
    for (int t = 0; t < 16; t++) {
        int idx = tid + t * 256;
        int r = idx >> 4, c4 = (idx & 15) << 2;
        cp16(smem_u32(kp_s + r * LQ + c4), Kg + (size_t)r * 1024 + c4);
    }
    CP_COMMIT();
    // v transposed: coalesced LDG.128, scalar STS (overlaps the cp.async)
#pragma unroll
    for (int t = 0; t < 16; t++) {
        int idx = tid + t * 256;
        int r = idx >> 4, c4 = (idx & 15) << 2;
        float4 v = *(const float4*)(Vg + (size_t)r * 1024 + c4);
        vt_s[(c4 + 0) * LP + r] = v.x;
        vt_s[(c4 + 1) * LP + r] = v.y;
        vt_s[(c4 + 2) * LP + r] = v.z;
        vt_s[(c4 + 3) * LP + r] = v.w;
    }
    CP_WAIT(0);
    __syncthreads();

    // ---- S = (q @ k^T) * 0.125 ---- warps: 2(M) x 4(N), each 32x64
    {
        const int wm = wid & 1, wn = wid >> 1;
        float acc[2][8][4];
#pragma unroll
        for (int a = 0; a < 2; a++)
#pragma unroll
            for (int n = 0; n < 8; n++)
#pragma unroll
                for (int k = 0; k < 4; k++) acc[a][n][k] = 0.f;

        const float* wA = q_s  + (wm * 32) * LQ;
        const float* wB = kp_s + (wn * 64) * LQ;
#pragma unroll
        for (int k8 = 0; k8 < 8; k8++) {
            int k0 = k8 * 8 + lc;
            uint32_t af[2][4], bf[8][2];
#pragma unroll
            for (int mi = 0; mi < 2; mi++) {
                const float* p = wA + (mi * 16 + lr) * LQ + k0;
                af[mi][0] = __float_as_uint(p[0]);
                af[mi][1] = __float_as_uint(p[8 * LQ]);
                af[mi][2] = __float_as_uint(p[4]);
                af[mi][3] = __float_as_uint(p[8 * LQ + 4]);
            }
#pragma unroll
            for (int ni = 0; ni < 8; ni++) {
                const float* p = wB + (ni * 8 + lr) * LQ + k0;
                bf[ni][0] = __float_as_uint(p[0]);
                bf[ni][1] = __float_as_uint(p[4]);
            }
#pragma unroll
            for (int mi = 0; mi < 2; mi++)
#pragma unroll
                for (int ni = 0; ni < 8; ni++)
                    mma8(acc[mi][ni], af[mi], bf[ni]);
        }
        __syncthreads();   // all k reads done before overwriting region as P
        float* Ps = kp_s;
#pragma unroll
        for (int mi = 0; mi < 2; mi++)
#pragma unroll
            for (int ni = 0; ni < 8; ni++) {
                int row = wm * 32 + mi * 16 + lr;
                int col = wn * 64 + ni * 8 + lc * 2;
                Ps[row * LP + col]           = acc[mi][ni][0] * 0.125f;
                Ps[row * LP + col + 1]       = acc[mi][ni][1] * 0.125f;
                Ps[(row + 8) * LP + col]     = acc[mi][ni][2] * 0.125f;
                Ps[(row + 8) * LP + col + 1] = acc[mi][ni][3] * 0.125f;
            }
    }
    __syncthreads();

    // ---- softmax over 256 cols; 4 lanes per row ----
    {
        float* p = kp_s + (tid >> 2) * LP + (tid & 3) * 64;
        float mx = -1e30f;
#pragma unroll 8
        for (int j = 0; j < 64; j++) mx = fmaxf(mx, p[j]);
        mx = fmaxf(mx, __shfl_xor_sync(0xffffffffu, mx, 1));
        mx = fmaxf(mx, __shfl_xor_sync(0xffffffffu, mx, 2));
        float sum = 0.f;
#pragma unroll 8
        for (int j = 0; j < 64; j++) { float e = __expf(p[j] - mx); p[j] = e; sum += e; }
        sum += __shfl_xor_sync(0xffffffffu, sum, 1);
        sum += __shfl_xor_sync(0xffffffffu, sum, 2);
        float inv = 1.f / sum;
#pragma unroll 8
        for (int j = 0; j < 64; j++) p[j] = f2tf(p[j] * inv);
    }
    __syncthreads();

    // ---- O = P @ V ---- warps: 4(M) x 2(N), each 16x32, k=256
    {
        const int wm = wid & 3, wn = wid >> 2;
        float acc[4][4];
#pragma unroll
        for (int n = 0; n < 4; n++)
#pragma unroll
            for (int k = 0; k < 4; k++) acc[n][k] = 0.f;

        const float* wA = kp_s + (wm * 16) * LP;
        const float* wB = vt_s + (wn * 32) * LP;
#pragma unroll 4
        for (int k8 = 0; k8 < 32; k8++) {
            int k0 = k8 * 8 + lc;
            uint32_t af[4];
            const float* pa = wA + lr * LP + k0;
            af[0] = __float_as_uint(pa[0]);
            af[1] = __float_as_uint(pa[8 * LP]);
            af[2] = __float_as_uint(pa[4]);
            af[3] = __float_as_uint(pa[8 * LP + 4]);
#pragma unroll
            for (int ni = 0; ni < 4; ni++) {
                const float* pb = wB + (ni * 8 + lr) * LP + k0;
                uint32_t bf[2] = { __float_as_uint(pb[0]), __float_as_uint(pb[4]) };
                mma8(acc[ni], af, bf);
            }
        }
        // shifted epilogue: out[b, r+63, h*64 + d], valid while r <= 1984
        const int hbase = h * 64 + wn * 32;
#pragma unroll
        for (int ni = 0; ni < 4; ni++) {
            int colg = hbase + ni * 8 + lc * 2;
            int r0 = c * 64 + wm * 16 + lr;
            if (r0 <= 1984) {
                float2 v; v.x = acc[ni][0]; v.y = acc[ni][1];
                *(float2*)(out + (size_t)(b * 2048 + r0 + 63) * 1024 + colg) = v;
            }
            int r1 = r0 + 8;
            if (r1 <= 1984) {
                float2 v; v.x = acc[ni][2]; v.y = acc[ni][3];
                *(float2*)(out + (size_t)(b * 2048 + r1 + 63) * 1024 + colg) = v;
            }
        }
    }
}

// -------------------------------- launcher ----------------------------------
extern "C" void kernel_launch(void* const* d_in, const int* in_sizes, int n_in,
                              void* d_out, int out_size) {
    const float* query = (const float*)d_in[0];
    const float* kv    = (const float*)d_in[1];
    const float* Wq    = (const float*)d_in[2];
    const float* bq    = (const float*)d_in[3];
    const float* Wk    = (const float*)d_in[4];
    const float* bk    = (const float*)d_in[5];
    const float* Wv    = (const float*)d_in[6];
    const float* bv    = (const float*)d_in[7];
    float* out = (float*)d_out;

    float *Aq, *Akv, *Wqc, *Wkc, *Wvc, *Qp, *Kp, *Vp;
    cudaGetSymbolAddress((void**)&Aq,  g_Aq);
    cudaGetSymbolAddress((void**)&Akv, g_Akv);
    cudaGetSymbolAddress((void**)&Wqc, g_Wqc);
    cudaGetSymbolAddress((void**)&Wkc, g_Wkc);
    cudaGetSymbolAddress((void**)&Wvc, g_Wvc);
    cudaGetSymbolAddress((void**)&Qp,  g_Qp);
    cudaGetSymbolAddress((void**)&Kp,  g_Kp);
    cudaGetSymbolAddress((void**)&Vp,  g_Vp);

    cudaFuncSetAttribute(gemm_tf32,  cudaFuncAttributeMaxDynamicSharedMemorySize, GEMM_SMEM);
    cudaFuncSetAttribute(attn_kernel, cudaFuncAttributeMaxDynamicSharedMemorySize, ATTN_SMEM);

    // 1) tf32-round + shift/pad activations and weights
    cvtq_kernel<<<8192, 256>>>(query, Aq);
    cvt_kernel <<<32768, 256>>>(kv, Akv, 32768 * 256);
    cvt_kernel <<<1024, 256>>>(Wq, Wqc, 256 * 1024);
    cvt_kernel <<<1024, 256>>>(Wk, Wkc, 256 * 1024);
    cvt_kernel <<<1024, 256>>>(Wv, Wvc, 256 * 1024);

    // 2) projections
    gemm_tf32<<<dim3(8, 64),  256, GEMM_SMEM>>>(Aq,  Wqc, bq, Qp);
    gemm_tf32<<<dim3(8, 256), 256, GEMM_SMEM>>>(Akv, Wkc, bk, Kp);
    gemm_tf32<<<dim3(8, 256), 256, GEMM_SMEM>>>(Akv, Wvc, bv, Vp);

    // 3) output head rows [0,63) zeroed; attention writes the rest
    zero_head<<<(4 * 63 * 256 + 255) / 256, 256>>>(out);
    attn_kernel<<<dim3(16, 32, 4), 256, ATTN_SMEM>>>(Qp, Kp, Vp, out);
}

// round 17
// speedup vs baseline: 1.8360x; 1.8360x over previous
#include <cuda_runtime.h>
#include <cuda_fp16.h>
#include <cstdint>

#define DEV __device__ __forceinline__

// ------------------------------- helpers -----------------------------------
DEV uint32_t smem_u32(const void* p) { return (uint32_t)__cvta_generic_to_shared(p); }

DEV void cp16(uint32_t dst, const void* src) {
    asm volatile("cp.async.cg.shared.global [%0], [%1], 16;" :: "r"(dst), "l"(src));
}
#define CP_COMMIT() asm volatile("cp.async.commit_group;")
#define CP_WAIT(N)  asm volatile("cp.async.wait_group %0;" :: "n"(N))

// fp16 mma: m16n8k16, fp32 accumulate
DEV void mma16(float* d, const uint32_t* a, const uint32_t* b) {
    asm volatile(
        "mma.sync.aligned.m16n8k16.row.col.f32.f16.f16.f32 "
        "{%0,%1,%2,%3}, {%4,%5,%6,%7}, {%8,%9}, {%0,%1,%2,%3};\n"
        : "+f"(d[0]), "+f"(d[1]), "+f"(d[2]), "+f"(d[3])
        : "r"(a[0]), "r"(a[1]), "r"(a[2]), "r"(a[3]), "r"(b[0]), "r"(b[1]));
}

DEV uint32_t h2_as_u32(__half2 h) { return *(uint32_t*)&h; }

// --------------------------- scratch (no cudaMalloc) ------------------------
__device__ __half g_Aq [8192ull  * 1024];   // shifted query rows, fp16
__device__ __half g_Akv[32768ull * 1024];   // kv rows, fp16
__device__ __half g_Wqc[1024 * 1024];
__device__ __half g_Wkc[1024 * 1024];
__device__ __half g_Wvc[1024 * 1024];
__device__ __half g_Qp [8192ull  * 1024];   // projections, fp16
__device__ __half g_Kp [32768ull * 1024];
__device__ __half g_Vp [32768ull * 1024];

// ----------------------------- convert kernels ------------------------------
__global__ void cvt_kernel(const float* __restrict__ src, __half* __restrict__ dst, int n4) {
    int i = blockIdx.x * 256 + threadIdx.x;
    if (i >= n4) return;
    float4 v = ((const float4*)src)[i];
    __half2 h01 = __floats2half2_rn(v.x, v.y);
    __half2 h23 = __floats2half2_rn(v.z, v.w);
    uint2 o; o.x = h2_as_u32(h01); o.y = h2_as_u32(h23);
    *(uint2*)(dst + (size_t)i * 4) = o;
}

// Aq row (b*2048 + j) = query[b, j+63] for j<1985 else 0, fp16
__global__ void cvtq_kernel(const float* __restrict__ query, __half* __restrict__ dst) {
    int i = blockIdx.x * 256 + threadIdx.x;   // float4 index over [8192,256]
    int col4 = i & 255;
    int row  = i >> 8;
    int b    = row >> 11;
    int j    = row & 2047;
    float4 v = make_float4(0.f, 0.f, 0.f, 0.f);
    if (j < 1985)
        v = ((const float4*)query)[(size_t)((b << 11) + j + 63) * 256 + col4];
    __half2 h01 = __floats2half2_rn(v.x, v.y);
    __half2 h23 = __floats2half2_rn(v.z, v.w);
    uint2 o; o.x = h2_as_u32(h01); o.y = h2_as_u32(h23);
    *(uint2*)(dst + (size_t)i * 4) = o;
}

// zero out[b, 0:63, :]
__global__ void zero_head(float* __restrict__ out) {
    int i = blockIdx.x * 256 + threadIdx.x;   // float4 index
    if (i >= 4 * 63 * 256) return;
    int b = i / (63 * 256);
    int r = i - b * (63 * 256);
    ((float4*)(out + (size_t)b * 2048 * 1024))[r] = make_float4(0.f, 0.f, 0.f, 0.f);
}

// ------ fp16 GEMM: C[M,1024] = A[M,1024] @ W[1024,1024]^T + bias (fp16 out) --
// BM=BN=128, BK=32 fp16, 3-stage cp.async, 8 warps of 32(M)x64(N).
constexpr int GK_LD    = 40;                       // halves per smem row (32+8 pad)
constexpr int GK_HSTG  = 128 * GK_LD;              // halves per operand per stage
constexpr int GEMM_SMEM = 3 * 2 * GK_HSTG * 2;     // 61440 B

__global__ void __launch_bounds__(256, 2)
gemm_fp16(const __half* __restrict__ A, const __half* __restrict__ B,
          const float* __restrict__ bias, __half* __restrict__ C) {
    extern __shared__ __half smh[];

    const int tid  = threadIdx.x;
    const int lane = tid & 31;
    const int wid  = tid >> 5;
    const int wm   = wid & 3;          // 4 warps along M
    const int wn   = wid >> 2;         // 2 warps along N
    const int lr   = lane >> 2;
    const int lc   = lane & 3;

    const __half* gA = A + (size_t)blockIdx.y * 128 * 1024;
    const __half* gB = B + (size_t)blockIdx.x * 128 * 1024;

    // loader: 512 16B-chunks per operand (128 rows x 4 chunks); 2 per thread.
    // chunk index = ldc0 + ch, ch in {0,1}; 16B = 8 halves.
    const int ldr0 = tid >> 1;                 // rows 0..127
    const int ldc0 = (tid & 1) * 2;            // chunk base: 0 or 2
    const uint32_t sA0 = smem_u32(smh);
    const uint32_t sB0 = sA0 + GK_HSTG * 2;    // bytes
    const uint32_t aOff = (uint32_t)(ldr0 * (GK_LD * 2) + ldc0 * 16);
    const __half* gAt = gA + (size_t)ldr0 * 1024 + ldc0 * 8;
    const __half* gBt = gB + (size_t)ldr0 * 1024 + ldc0 * 8;

    float acc[2][8][4];
#pragma unroll
    for (int a = 0; a < 2; a++)
#pragma unroll
        for (int n = 0; n < 8; n++)
#pragma unroll
            for (int c = 0; c < 4; c++) acc[a][n][c] = 0.f;

#pragma unroll
    for (int s = 0; s < 2; s++) {              // prefetch stages 0,1
        uint32_t stb = s * (2 * GK_HSTG * 2);
        int kb = s * 32;
#pragma unroll
        for (int ch = 0; ch < 2; ch++) {
            cp16(sA0 + stb + aOff + ch * 16, gAt + kb + ch * 8);
            cp16(sB0 + stb + aOff + ch * 16, gBt + kb + ch * 8);
        }
        CP_COMMIT();
    }

#pragma unroll 1
    for (int kt = 0; kt < 32; kt++) {
        CP_WAIT(1);
        __syncthreads();
        {
            int kn = kt + 2;
            if (kn < 32) {
                uint32_t stb = (kn % 3) * (2 * GK_HSTG * 2);
                int kb = kn * 32;
#pragma unroll
                for (int ch = 0; ch < 2; ch++) {
                    cp16(sA0 + stb + aOff + ch * 16, gAt + kb + ch * 8);
                    cp16(sB0 + stb + aOff + ch * 16, gBt + kb + ch * 8);
                }
            }
            CP_COMMIT();
        }
        const int stage = kt % 3;
        const __half* wA = smh + stage * (2 * GK_HSTG) + (wm * 32) * GK_LD;
        const __half* wB = smh + stage * (2 * GK_HSTG) + GK_HSTG + (wn * 64) * GK_LD;
#pragma unroll
        for (int kk = 0; kk < 2; kk++) {       // two k16 steps per BK=32
            const int k0 = kk * 16 + lc * 2;
            uint32_t af[2][4];
            uint32_t bf[8][2];
#pragma unroll
            for (int mi = 0; mi < 2; mi++) {
                const __half* p = wA + (mi * 16 + lr) * GK_LD + k0;
                af[mi][0] = *(const uint32_t*)(p);
                af[mi][1] = *(const uint32_t*)(p + 8 * GK_LD);
                af[mi][2] = *(const uint32_t*)(p + 8);
                af[mi][3] = *(const uint32_t*)(p + 8 * GK_LD + 8);
            }
#pragma unroll
            for (int ni = 0; ni < 8; ni++) {
                const __half* p = wB + (ni * 8 + lr) * GK_LD + k0;
                bf[ni][0] = *(const uint32_t*)(p);
                bf[ni][1] = *(const uint32_t*)(p + 8);
            }
#pragma unroll
            for (int mi = 0; mi < 2; mi++)
#pragma unroll
                for (int ni = 0; ni < 8; ni++)
                    mma16(acc[mi][ni], af[mi], bf[ni]);
        }
    }

    // epilogue: +bias (fp32), round to fp16
    const int mbase = blockIdx.y * 128 + wm * 32;
    const int nbase = blockIdx.x * 128 + wn * 64;
#pragma unroll
    for (int ni = 0; ni < 8; ni++) {
        int col = nbase + ni * 8 + lc * 2;
        float bx = bias[col];
        float by = bias[col + 1];
#pragma unroll
        for (int mi = 0; mi < 2; mi++) {
            int r0 = mbase + mi * 16 + lr;
            __half2 v0 = __floats2half2_rn(acc[mi][ni][0] + bx, acc[mi][ni][1] + by);
            __half2 v1 = __floats2half2_rn(acc[mi][ni][2] + bx, acc[mi][ni][3] + by);
            *(uint32_t*)(C + (size_t)r0 * 1024 + col)       = h2_as_u32(v0);
            *(uint32_t*)(C + (size_t)(r0 + 8) * 1024 + col) = h2_as_u32(v1);
        }
    }
}

// -------------------------------- attention ---------------------------------
// One CTA per (head, chunk, batch). 256 threads (8 warps). fp16 operands.
// smem: q[64x72]h | k[256x72]h (reused as P[64x264]h) | vT[64x264]h | S[64x260]f
constexpr int LQH = 72;    // halves
constexpr int LPH = 264;   // halves
constexpr int LSF = 260;   // floats
constexpr int ATTN_Q_B = 64 * LQH * 2;       // 9216
constexpr int ATTN_K_B = 256 * LQH * 2;      // 36864
constexpr int ATTN_V_B = 64 * LPH * 2;       // 33792
constexpr int ATTN_S_B = 64 * LSF * 4;       // 66560
constexpr int ATTN_SMEM = ATTN_Q_B + ATTN_K_B + ATTN_V_B + ATTN_S_B;   // 146432

__global__ void __launch_bounds__(256, 1)
attn_kernel(const __half* __restrict__ Qp, const __half* __restrict__ Kp,
            const __half* __restrict__ Vp, float* __restrict__ out) {
    extern __shared__ char smc[];
    __half* q_h  = (__half*)smc;                         // 64*72
    __half* k_h  = q_h + 64 * LQH;                       // 256*72 (reused as P 64*264)
    __half* vt_h = k_h + 256 * LQH;                      // 64*264
    float*  S_f  = (float*)(smc + ATTN_Q_B + ATTN_K_B + ATTN_V_B);   // 64*260

    const int h = blockIdx.x, c = blockIdx.y, b = blockIdx.z;
    const int tid = threadIdx.x, lane = tid & 31, wid = tid >> 5;
    const int lr = lane >> 2, lc = lane & 3;

    const __half* Qg = Qp + (size_t)(b * 2048 + c * 64) * 1024 + h * 64;
    const __half* Kg = Kp + (size_t)((b * 32 + c) * 256) * 1024 + h * 64;
    const __half* Vg = Vp + (size_t)((b * 32 + c) * 256) * 1024 + h * 64;

    // q: 64 rows x 8 chunks(16B) = 512 cp16
#pragma unroll
    for (int t = 0; t < 2; t++) {
        int idx = tid + t * 256;
        int r = idx >> 3, ch = idx & 7;
        cp16(smem_u32(q_h) + (uint32_t)(r * (LQH * 2) + ch * 16),
             Qg + (size_t)r * 1024 + ch * 8);
    }
    // k: 256 rows x 8 chunks = 2048 cp16
#pragma unroll
    for (int t = 0; t < 8; t++) {
        int idx = tid + t * 256;
        int r = idx >> 3, ch = idx & 7;
        cp16(smem_u32(k_h) + (uint32_t)(r * (LQH * 2) + ch * 16),
             Kg + (size_t)r * 1024 + ch * 8);
    }
    CP_COMMIT();
    // v transposed: LDG.64 (4 halves), scalar STS
#pragma unroll
    for (int t = 0; t < 16; t++) {
        int idx = tid + t * 256;
        int r = idx >> 4, c4 = (idx & 15) << 2;
        uint2 raw = *(const uint2*)(Vg + (size_t)r * 1024 + c4);
        __half hv[4];
        *(uint2*)hv = raw;
        vt_h[(c4 + 0) * LPH + r] = hv[0];
        vt_h[(c4 + 1) * LPH + r] = hv[1];
        vt_h[(c4 + 2) * LPH + r] = hv[2];
        vt_h[(c4 + 3) * LPH + r] = hv[3];
    }
    CP_WAIT(0);
    __syncthreads();

    // ---- S = (q @ k^T) * 0.125 -> S_f ---- warps: 2(M) x 4(N), each 32x64
    {
        const int wm = wid & 1, wn = wid >> 1;
        float acc[2][8][4];
#pragma unroll
        for (int a = 0; a < 2; a++)
#pragma unroll
            for (int n = 0; n < 8; n++)
#pragma unroll
                for (int k = 0; k < 4; k++) acc[a][n][k] = 0.f;

        const __half* wA = q_h + (wm * 32) * LQH;
        const __half* wB = k_h + (wn * 64) * LQH;
#pragma unroll
        for (int k8 = 0; k8 < 4; k8++) {       // 4 k16 steps over 64
            int k0 = k8 * 16 + lc * 2;
            uint32_t af[2][4], bf[8][2];
#pragma unroll
            for (int mi = 0; mi < 2; mi++) {
                const __half* p = wA + (mi * 16 + lr) * LQH + k0;
                af[mi][0] = *(const uint32_t*)(p);
                af[mi][1] = *(const uint32_t*)(p + 8 * LQH);
                af[mi][2] = *(const uint32_t*)(p + 8);
                af[mi][3] = *(const uint32_t*)(p + 8 * LQH + 8);
            }
#pragma unroll
            for (int ni = 0; ni < 8; ni++) {
                const __half* p = wB + (ni * 8 + lr) * LQH + k0;
                bf[ni][0] = *(const uint32_t*)(p);
                bf[ni][1] = *(const uint32_t*)(p + 8);
            }
#pragma unroll
            for (int mi = 0; mi < 2; mi++)
#pragma unroll
                for (int ni = 0; ni < 8; ni++)
                    mma16(acc[mi][ni], af[mi], bf[ni]);
        }
#pragma unroll
        for (int mi = 0; mi < 2; mi++)
#pragma unroll
            for (int ni = 0; ni < 8; ni++) {
                int row = wm * 32 + mi * 16 + lr;
                int col = wn * 64 + ni * 8 + lc * 2;
                S_f[row * LSF + col]           = acc[mi][ni][0] * 0.125f;
                S_f[row * LSF + col + 1]       = acc[mi][ni][1] * 0.125f;
                S_f[(row + 8) * LSF + col]     = acc[mi][ni][2] * 0.125f;
                S_f[(row + 8) * LSF + col + 1] = acc[mi][ni][3] * 0.125f;
            }
    }
    __syncthreads();   // all S written; all k_h reads done -> safe to overwrite as P

    // ---- softmax over 256 cols; 4 lanes/row, interleaved cols (conflict-free) ----
    {
        const int row = tid >> 2, l4 = tid & 3;
        const float* ps = S_f + row * LSF + l4;
        __half* pp = k_h + row * LPH + l4;     // P fp16, ld 264
        float mx = -1e30f;
#pragma unroll 8
        for (int j = 0; j < 64; j++) mx = fmaxf(mx, ps[j * 4]);
        mx = fmaxf(mx, __shfl_xor_sync(0xffffffffu, mx, 1));
        mx = fmaxf(mx, __shfl_xor_sync(0xffffffffu, mx, 2));
        float e[64];
        float sum = 0.f;
#pragma unroll 8
        for (int j = 0; j < 64; j++) { e[j] = __expf(ps[j * 4] - mx); sum += e[j]; }
        sum += __shfl_xor_sync(0xffffffffu, sum, 1);
        sum += __shfl_xor_sync(0xffffffffu, sum, 2);
        float inv = 1.f / sum;
#pragma unroll 8
        for (int j = 0; j < 64; j++) pp[j * 4] = __float2half_rn(e[j] * inv);
    }
    __syncthreads();

    // ---- O = P @ V ---- warps: 4(M) x 2(N), each 16x32, k=256
    {
        const int wm = wid & 3, wn = wid >> 2;
        float acc[4][4];
#pragma unroll
        for (int n = 0; n < 4; n++)
#pragma unroll
            for (int k = 0; k < 4; k++) acc[n][k] = 0.f;

        const __half* wA = k_h + (wm * 16) * LPH;     // P
        const __half* wB = vt_h + (wn * 32) * LPH;
#pragma unroll 4
        for (int k8 = 0; k8 < 16; k8++) {             // 16 k16 steps over 256
            int k0 = k8 * 16 + lc * 2;
            uint32_t af[4];
            const __half* pa = wA + lr * LPH + k0;
            af[0] = *(const uint32_t*)(pa);
            af[1] = *(const uint32_t*)(pa + 8 * LPH);
            af[2] = *(const uint32_t*)(pa + 8);
            af[3] = *(const uint32_t*)(pa + 8 * LPH + 8);
#pragma unroll
            for (int ni = 0; ni < 4; ni++) {
                const __half* pb = wB + (ni * 8 + lr) * LPH + k0;
                uint32_t bf[2] = { *(const uint32_t*)(pb), *(const uint32_t*)(pb + 8) };
                mma16(acc[ni], af, bf);
            }
        }
        // shifted epilogue: out[b, r+63, h*64 + d], valid while r <= 1984
        const int hbase = h * 64 + wn * 32;
#pragma unroll
        for (int ni = 0; ni < 4; ni++) {
            int colg = hbase + ni * 8 + lc * 2;
            int r0 = c * 64 + wm * 16 + lr;
            if (r0 <= 1984) {
                float2 v; v.x = acc[ni][0]; v.y = acc[ni][1];
                *(float2*)(out + (size_t)(b * 2048 + r0 + 63) * 1024 + colg) = v;
            }
            int r1 = r0 + 8;
            if (r1 <= 1984) {
                float2 v; v.x = acc[ni][2]; v.y = acc[ni][3];
                *(float2*)(out + (size_t)(b * 2048 + r1 + 63) * 1024 + colg) = v;
            }
        }
    }
}

// -------------------------------- launcher ----------------------------------
extern "C" void kernel_launch(void* const* d_in, const int* in_sizes, int n_in,
                              void* d_out, int out_size) {
    const float* query = (const float*)d_in[0];
    const float* kv    = (const float*)d_in[1];
    const float* Wq    = (const float*)d_in[2];
    const float* bq    = (const float*)d_in[3];
    const float* Wk    = (const float*)d_in[4];
    const float* bk    = (const float*)d_in[5];
    const float* Wv    = (const float*)d_in[6];
    const float* bv    = (const float*)d_in[7];
    float* out = (float*)d_out;

    __half *Aq, *Akv, *Wqc, *Wkc, *Wvc, *Qp, *Kp, *Vp;
    cudaGetSymbolAddress((void**)&Aq,  g_Aq);
    cudaGetSymbolAddress((void**)&Akv, g_Akv);
    cudaGetSymbolAddress((void**)&Wqc, g_Wqc);
    cudaGetSymbolAddress((void**)&Wkc, g_Wkc);
    cudaGetSymbolAddress((void**)&Wvc, g_Wvc);
    cudaGetSymbolAddress((void**)&Qp,  g_Qp);
    cudaGetSymbolAddress((void**)&Kp,  g_Kp);
    cudaGetSymbolAddress((void**)&Vp,  g_Vp);

    cudaFuncSetAttribute(gemm_fp16,  cudaFuncAttributeMaxDynamicSharedMemorySize, GEMM_SMEM);
    cudaFuncSetAttribute(attn_kernel, cudaFuncAttributeMaxDynamicSharedMemorySize, ATTN_SMEM);

    // 1) fp16-round + shift/pad activations and weights
    cvtq_kernel<<<8192, 256>>>(query, Aq);
    cvt_kernel <<<32768, 256>>>(kv, Akv, 32768 * 256);
    cvt_kernel <<<1024, 256>>>(Wq, Wqc, 256 * 1024);
    cvt_kernel <<<1024, 256>>>(Wk, Wkc, 256 * 1024);
    cvt_kernel <<<1024, 256>>>(Wv, Wvc, 256 * 1024);

    // 2) projections (fp16 tensor cores; blockIdx.x-fast keeps A tile in L2)
    gemm_fp16<<<dim3(8, 64),  256, GEMM_SMEM>>>(Aq,  Wqc, bq, Qp);
    gemm_fp16<<<dim3(8, 256), 256, GEMM_SMEM>>>(Akv, Wkc, bk, Kp);
    gemm_fp16<<<dim3(8, 256), 256, GEMM_SMEM>>>(Akv, Wvc, bv, Vp);

    // 3) output head rows [0,63) zeroed; attention writes the rest
    zero_head<<<(4 * 63 * 256 + 255) / 256, 256>>>(out);
    attn_kernel<<<dim3(16, 32, 4), 256, ATTN_SMEM>>>(Qp, Kp, Vp, out);
}